// round 4
// baseline (speedup 1.0000x reference)
#include <cuda_runtime.h>

#define CLS   15
#define KTOP  13
#define MAXB  8
#define MAXN  64
#define MAXL  21504
#define MAXBL (MAXB*MAXL)

// ---------------- device scratch (static, no allocation) ----------------
__device__ float g_minx[MAXB*MAXN], g_maxx_[MAXB*MAXN], g_miny[MAXB*MAXN], g_maxy[MAXB*MAXN];
__device__ float g_area[MAXB*MAXN], g_cosr[MAXB*MAXN], g_sinr[MAXB*MAXN];
__device__ float g_cx[MAXB*MAXN], g_cy[MAXB*MAXN], g_hw[MAXB*MAXN], g_hh[MAXB*MAXN], g_pad[MAXB*MAXN];
__device__ float g_box5[MAXB*MAXN*5];
__device__ int   g_lab[MAXB*MAXN], g_crowd[MAXB*MAXN];

__device__ float4 d_aabb[MAXBL];     // anchor pseudo-corner AABB (mnx,mxx,mny,mxy)
__device__ float  d_parea[MAXBL];    // anchor w*h
__device__ float  d_M[(size_t)MAXB*MAXN*MAXL];   // metric * inside (topk input)
__device__ unsigned long long d_bits[MAXBL];     // topk membership bitmask per anchor
__device__ int    d_agi[MAXBL];
__device__ float  d_mv[MAXBL], d_iv[MAXBL];
__device__ unsigned char d_fl[MAXBL];
__device__ unsigned int d_maxm[MAXB*MAXN], d_maxi[MAXB*MAXN];

// ---------------- init ----------------
__global__ void k_init() {
    int i = blockIdx.x * blockDim.x + threadIdx.x;
    if (i < MAXBL) d_bits[i] = 0ull;
    if (i < MAXB*MAXN) { d_maxm[i] = 0u; d_maxi[i] = 0u; }
}

// ---------------- gt preprocess ----------------
__global__ void k_gt(const float* __restrict__ gtb, const int* __restrict__ glab,
                     const int* __restrict__ gcrowd, const float* __restrict__ pad,
                     int B, int n) {
    __shared__ int s_is64;
    int tid = threadIdx.x;
    int tot = B * n;
    if (tid == 0) {
        // int64 labels (x64 on) have zero high words at odd int32 positions.
        int is64 = 1;
        for (int i = 1; i < tot; i += 2) if (glab[i] != 0) { is64 = 0; break; }
        s_is64 = is64;
    }
    __syncthreads();
    int is64 = s_is64;
    for (int i = tid; i < tot; i += blockDim.x) {
        float cx = gtb[i*5+0], cy = gtb[i*5+1], w = gtb[i*5+2], h = gtb[i*5+3], r = gtb[i*5+4];
        float cr = cosf(r), sr = sinf(r);
        float dx = 0.5f*w*cr, dy = 0.5f*h*sr;
        float mnx = 1e30f, mxx = -1e30f, mny = 1e30f, mxy = -1e30f;
        #pragma unroll
        for (int c = 0; c < 4; c++) {
            float ox = (c==1||c==2) ?  dx : -dx;
            float oy = (c>=2)       ?  dy : -dy;
            float xr = cx + ox*cr - oy*sr;
            float yr = cy + ox*sr + oy*cr;
            mnx = fminf(mnx,xr); mxx = fmaxf(mxx,xr);
            mny = fminf(mny,yr); mxy = fmaxf(mxy,yr);
        }
        g_minx[i]=mnx; g_maxx_[i]=mxx; g_miny[i]=mny; g_maxy[i]=mxy;
        g_area[i]=w*h; g_cosr[i]=cr; g_sinr[i]=sr;
        g_cx[i]=cx; g_cy[i]=cy; g_hw[i]=0.5f*w; g_hh[i]=0.5f*h;
        g_pad[i]=pad[i];
        g_lab[i]   = is64 ? glab[2*i] : glab[i];
        g_crowd[i] = gcrowd[i];
        #pragma unroll
        for (int j = 0; j < 5; j++) g_box5[i*5+j] = gtb[i*5+j];
    }
}

// ---------------- metric matrix + anchor AABBs ----------------
__global__ void k_metric(const float* __restrict__ prb, const float* __restrict__ psc,
                         const float* __restrict__ apts, int B, int n, int L, int apb) {
    __shared__ float s_mnx[MAXN], s_mxx[MAXN], s_mny[MAXN], s_mxy[MAXN], s_ar[MAXN];
    __shared__ float s_cr[MAXN], s_sr[MAXN], s_cx[MAXN], s_cy[MAXN], s_hw[MAXN], s_hh[MAXN];
    __shared__ int   s_lab[MAXN];
    int b = blockIdx.x / apb;
    int a = (blockIdx.x % apb) * blockDim.x + threadIdx.x;
    if ((int)threadIdx.x < n) {
        int i = b*n + threadIdx.x;
        s_mnx[threadIdx.x]=g_minx[i]; s_mxx[threadIdx.x]=g_maxx_[i];
        s_mny[threadIdx.x]=g_miny[i]; s_mxy[threadIdx.x]=g_maxy[i];
        s_ar[threadIdx.x]=g_area[i];  s_cr[threadIdx.x]=g_cosr[i]; s_sr[threadIdx.x]=g_sinr[i];
        s_cx[threadIdx.x]=g_cx[i];    s_cy[threadIdx.x]=g_cy[i];
        s_hw[threadIdx.x]=g_hw[i];    s_hh[threadIdx.x]=g_hh[i];
        s_lab[threadIdx.x]=g_lab[i];
    }
    __syncthreads();
    if (a >= L) return;
    size_t ba = (size_t)b*L + a;
    float cx = prb[ba*5+0], cy = prb[ba*5+1], w = prb[ba*5+2], h = prb[ba*5+3], r = prb[ba*5+4];
    float cr = cosf(r), sr = sinf(r);
    float dx = 0.5f*w*cr, dy = 0.5f*h*sr;
    float mnx = 1e30f, mxx = -1e30f, mny = 1e30f, mxy = -1e30f;
    #pragma unroll
    for (int c = 0; c < 4; c++) {
        float ox = (c==1||c==2) ?  dx : -dx;
        float oy = (c>=2)       ?  dy : -dy;
        float xr = cx + ox*cr - oy*sr;
        float yr = cy + ox*sr + oy*cr;
        mnx = fminf(mnx,xr); mxx = fmaxf(mxx,xr);
        mny = fminf(mny,yr); mxy = fmaxf(mxy,yr);
    }
    float parea = w*h;
    d_aabb[ba]  = make_float4(mnx, mxx, mny, mxy);
    d_parea[ba] = parea;
    float px = apts[2*a], py = apts[2*a+1];
    for (int g = 0; g < n; g++) {
        float iw = fmaxf(fminf(mxx, s_mxx[g]) - fmaxf(mnx, s_mnx[g]), 0.0f);
        float ih = fmaxf(fminf(mxy, s_mxy[g]) - fmaxf(mny, s_mny[g]), 0.0f);
        float inter = iw * ih;
        float iou = inter / (s_ar[g] + parea - inter + 1e-9f);
        iou = fminf(fmaxf(iou, 0.0f), 1.0f);
        float ddx = px - s_cx[g], ddy = py - s_cy[g];
        float xl =  ddx*s_cr[g] + ddy*s_sr[g];
        float yl = -ddx*s_sr[g] + ddy*s_cr[g];
        bool ins = (fabsf(xl) <= s_hw[g]) && (fabsf(yl) <= s_hh[g]);
        float sc = psc[ba*CLS + s_lab[g]];
        float i2 = iou*iou;
        float m  = sc * i2*i2*i2;
        d_M[((size_t)(b*n + g))*L + a] = ins ? m : 0.0f;
    }
}

// ---------------- top-13 per (b,g), tie-break lowest index ----------------
__global__ void k_topk(int B, int n, int L) {
    int b = blockIdx.x / n, g = blockIdx.x % n;
    const float* row = d_M + ((size_t)(b*n + g)) * L;
    float lv[KTOP]; int li[KTOP];
    #pragma unroll
    for (int k = 0; k < KTOP; k++) { lv[k] = -1.0f; li[k] = 0x7fffffff; }
    for (int a = threadIdx.x; a < L; a += 256) {
        float v = row[a];
        if (v > lv[KTOP-1] || (v == lv[KTOP-1] && a < li[KTOP-1])) {
            int p = KTOP-1;
            while (p > 0 && (v > lv[p-1] || (v == lv[p-1] && a < li[p-1]))) {
                lv[p] = lv[p-1]; li[p] = li[p-1]; p--;
            }
            lv[p] = v; li[p] = a;
        }
    }
    __shared__ float sv[256*KTOP];
    __shared__ int   si[256*KTOP];
    #pragma unroll
    for (int k = 0; k < KTOP; k++) { sv[threadIdx.x*KTOP+k] = lv[k]; si[threadIdx.x*KTOP+k] = li[k]; }
    for (int s = 128; s > 0; s >>= 1) {
        __syncthreads();
        if ((int)threadIdx.x < s) {
            int ba_ = threadIdx.x*KTOP, bb_ = (threadIdx.x+s)*KTOP;
            float ov[KTOP]; int oi[KTOP];
            int ia = 0, ib = 0;
            #pragma unroll
            for (int k = 0; k < KTOP; k++) {
                bool ta;
                if (ia >= KTOP) ta = false;
                else if (ib >= KTOP) ta = true;
                else {
                    float av = sv[ba_+ia], bv = sv[bb_+ib];
                    ta = (av > bv) || (av == bv && si[ba_+ia] < si[bb_+ib]);
                }
                if (ta) { ov[k] = sv[ba_+ia]; oi[k] = si[ba_+ia]; ia++; }
                else    { ov[k] = sv[bb_+ib]; oi[k] = si[bb_+ib]; ib++; }
            }
            #pragma unroll
            for (int k = 0; k < KTOP; k++) { sv[ba_+k] = ov[k]; si[ba_+k] = oi[k]; }
        }
    }
    __syncthreads();
    if (threadIdx.x == 0 && g_pad[b*n + g] > 0.0f) {
        for (int k = 0; k < KTOP; k++) {
            int idx = si[k];
            if (idx >= 0 && idx < L)
                atomicOr(&d_bits[(size_t)b*L + idx], 1ull << g);
        }
    }
}

// ---------------- per-anchor assignment + per-gt max reductions ----------------
__global__ void k_assign(const float* __restrict__ psc, const float* __restrict__ apts,
                         int B, int n, int L, int apb) {
    __shared__ float s_mnx[MAXN], s_mxx[MAXN], s_mny[MAXN], s_mxy[MAXN], s_ar[MAXN];
    __shared__ float s_cr[MAXN], s_sr[MAXN], s_cx[MAXN], s_cy[MAXN], s_hw[MAXN], s_hh[MAXN];
    __shared__ int   s_lab[MAXN];
    int b = blockIdx.x / apb;
    int a = (blockIdx.x % apb) * blockDim.x + threadIdx.x;
    if ((int)threadIdx.x < n) {
        int i = b*n + threadIdx.x;
        s_mnx[threadIdx.x]=g_minx[i]; s_mxx[threadIdx.x]=g_maxx_[i];
        s_mny[threadIdx.x]=g_miny[i]; s_mxy[threadIdx.x]=g_maxy[i];
        s_ar[threadIdx.x]=g_area[i];  s_cr[threadIdx.x]=g_cosr[i]; s_sr[threadIdx.x]=g_sinr[i];
        s_cx[threadIdx.x]=g_cx[i];    s_cy[threadIdx.x]=g_cy[i];
        s_hw[threadIdx.x]=g_hw[i];    s_hh[threadIdx.x]=g_hh[i];
        s_lab[threadIdx.x]=g_lab[i];
    }
    __syncthreads();
    if (a >= L) return;
    size_t ba = (size_t)b*L + a;
    float4 ab = d_aabb[ba];
    float pa = d_parea[ba];
    float px = apts[2*a], py = apts[2*a+1];
    unsigned long long bits = d_bits[ba];
    int s = 0, g1 = -1;
    unsigned long long t = bits;
    while (t) {
        int g = __ffsll((long long)t) - 1; t &= t - 1;
        float ddx = px - s_cx[g], ddy = py - s_cy[g];
        float xl =  ddx*s_cr[g] + ddy*s_sr[g];
        float yl = -ddx*s_sr[g] + ddy*s_cr[g];
        if (fabsf(xl) <= s_hw[g] && fabsf(yl) <= s_hh[g]) { if (s == 0) g1 = g; s++; }
    }
    int agi = 0; unsigned char fl = 0; float mv = 0.0f, iv = 0.0f;
    if (s == 1) agi = g1;
    else if (s > 1) {
        // replaced by one-hot of argmax-iou over ALL gts (first max wins)
        float best = -1e30f;
        for (int g = 0; g < n; g++) {
            float iw = fmaxf(fminf(ab.y, s_mxx[g]) - fmaxf(ab.x, s_mnx[g]), 0.0f);
            float ih = fmaxf(fminf(ab.w, s_mxy[g]) - fmaxf(ab.z, s_mny[g]), 0.0f);
            float inter = iw * ih;
            float iou = inter / (s_ar[g] + pa - inter + 1e-9f);
            iou = fminf(fmaxf(iou, 0.0f), 1.0f);
            if (iou > best) { best = iou; agi = g; }
        }
    }
    if (s > 0) {
        fl = 1;
        float iw = fmaxf(fminf(ab.y, s_mxx[agi]) - fmaxf(ab.x, s_mnx[agi]), 0.0f);
        float ih = fmaxf(fminf(ab.w, s_mxy[agi]) - fmaxf(ab.z, s_mny[agi]), 0.0f);
        float inter = iw * ih;
        float iou = inter / (s_ar[agi] + pa - inter + 1e-9f);
        iou = fminf(fmaxf(iou, 0.0f), 1.0f);
        float sc = psc[ba*CLS + s_lab[agi]];
        float i2 = iou*iou;
        mv = sc * i2*i2*i2;
        iv = iou;
        atomicMax(&d_maxm[b*n + agi], __float_as_uint(mv));
        atomicMax(&d_maxi[b*n + agi], __float_as_uint(iv));
    }
    d_agi[ba] = agi; d_fl[ba] = fl; d_mv[ba] = mv; d_iv[ba] = iv;
}

// ---------------- outputs ----------------
__global__ void k_out(float* __restrict__ out, int B, int n, int L, int apb) {
    int b = blockIdx.x / apb;
    int a = (blockIdx.x % apb) * blockDim.x + threadIdx.x;
    if (a >= L) return;
    size_t ba = (size_t)b*L + a;
    size_t BL = (size_t)B * L;
    int agi = d_agi[ba];
    int fl  = d_fl[ba];
    int gi  = b*n + agi;
    float mm = __uint_as_float(d_maxm[gi]);
    float mi = __uint_as_float(d_maxi[gi]);
    float per_anchor = fl ? d_mv[ba] / (mm + 1e-9f) * mi : 0.0f;
    int lab = fl ? g_lab[gi] : CLS;
    int crowd = g_crowd[gi];
    // assigned_labels
    out[ba] = (float)lab;
    // assigned_rboxes
    #pragma unroll
    for (int j = 0; j < 5; j++) out[BL + ba*5 + j] = g_box5[gi*5 + j];
    // assigned_scores (one-hot over kept 15 classes) * per_anchor * (crowd==0)
    float sval = (crowd == 0) ? per_anchor : 0.0f;
    #pragma unroll
    for (int j = 0; j < CLS; j++)
        out[6*BL + ba*CLS + j] = (fl && j == lab) ? sval : 0.0f;
    // assigned_gt_index
    out[21*BL + ba] = (float)agi;
    // assigned_crowd
    out[22*BL + ba] = (float)crowd;
}

// ---------------- launch ----------------
extern "C" void kernel_launch(void* const* d_in, const int* in_sizes, int n_in,
                              void* d_out, int out_size) {
    const float* psc    = (const float*)d_in[0];  // pred_scores  (B,L,15)
    const float* prb    = (const float*)d_in[1];  // pred_rboxes  (B,L,5)
    const float* apts   = (const float*)d_in[2];  // anchor_points (L,2)
    const int*   glab   = (const int*)  d_in[3];  // gt_labels (int32 or int64-detected)
    const float* gtb    = (const float*)d_in[4];  // gt_bboxes (B,n,5)
    const int*   gcrowd = (const int*)  d_in[6];  // gt_crowd (B,n,1) int32
    const float* pad    = (const float*)d_in[7];  // pad_gt_mask (B,n,1)

    int L = in_sizes[2] / 2;
    int B = in_sizes[0] / (L * CLS);
    int n = in_sizes[4] / (B * 5);
    int apb = (L + 255) / 256;

    k_init  <<<(MAXBL + 255) / 256, 256>>>();
    k_gt    <<<1, 512>>>(gtb, glab, gcrowd, pad, B, n);
    k_metric<<<B * apb, 256>>>(prb, psc, apts, B, n, L, apb);
    k_topk  <<<B * n, 256>>>(B, n, L);
    k_assign<<<B * apb, 256>>>(psc, apts, B, n, L, apb);
    k_out   <<<B * apb, 256>>>((float*)d_out, B, n, L, apb);
    (void)n_in; (void)out_size;
}